// round 2
// baseline (speedup 1.0000x reference)
#include <cuda_runtime.h>
#include <mma.h>
#include <math.h>

using namespace nvcuda;

// Problem dims
#define DD 256
#define TT 128
#define NROWS 131072   // B*A*T = 8*128*128
#define NBA   1024     // B*A

// MLP kernel tiling
#define LDX 260
#define LDH 68
#define MLP_SMEM_BYTES ((64*LDX + 64*LDH + 64*LDX)*4)

__device__ float g_yo[NBA * DD];

// ---------------------------------------------------------------------------
// Kernel 1: yo[b,a,:] = ((cx @ wkv)[:, D:2D] + bkv[D:2D]) @ wo + bo
// 16 (b,a) rows per block, 256 threads (thread = output column).
// ---------------------------------------------------------------------------
__global__ void yo_kernel(const float* __restrict__ cx, const float* __restrict__ wkv,
                          const float* __restrict__ bkv, const float* __restrict__ wo,
                          const float* __restrict__ bo) {
    __shared__ float sCX[16][DD];
    __shared__ float sV[16][DD];
    int tid = threadIdx.x;
    int r0 = blockIdx.x * 16;

    #pragma unroll
    for (int i = 0; i < 16; i++) sCX[i][tid] = cx[(r0 + i) * DD + tid];
    __syncthreads();

    float acc[16];
    #pragma unroll
    for (int r = 0; r < 16; r++) acc[r] = bkv[DD + tid];
    for (int c = 0; c < DD; c++) {
        float wv = wkv[c * 512 + DD + tid];   // V half of wkv
        #pragma unroll
        for (int r = 0; r < 16; r++) acc[r] += sCX[r][c] * wv;
    }
    #pragma unroll
    for (int r = 0; r < 16; r++) sV[r][tid] = acc[r];
    __syncthreads();

    float acc2[16];
    #pragma unroll
    for (int r = 0; r < 16; r++) acc2[r] = bo[tid];
    for (int k = 0; k < DD; k++) {
        float wv = wo[k * DD + tid];
        #pragma unroll
        for (int r = 0; r < 16; r++) acc2[r] += sV[r][k] * wv;
    }
    #pragma unroll
    for (int r = 0; r < 16; r++) g_yo[(r0 + r) * DD + tid] = acc2[r];
}

// ---------------------------------------------------------------------------
// Kernel 2: x3 = LN2( LN1(x) + yo[b,a] )   -> written into out (residual base)
// One warp per row (256 elems, 8 per lane).
// ---------------------------------------------------------------------------
__global__ void prep_kernel(const float* __restrict__ x,
                            const float* __restrict__ ln1w, const float* __restrict__ ln1b,
                            const float* __restrict__ ln2w, const float* __restrict__ ln2b,
                            float* __restrict__ out) {
    int warp = threadIdx.x >> 5;
    int lane = threadIdx.x & 31;
    long row = (long)blockIdx.x * 8 + warp;
    const float* xr = x + row * DD;

    float v[8];
    float s = 0.f, sq = 0.f;
    #pragma unroll
    for (int j = 0; j < 8; j++) {
        v[j] = xr[lane + 32 * j];
        s += v[j]; sq += v[j] * v[j];
    }
    #pragma unroll
    for (int o = 16; o > 0; o >>= 1) {
        s  += __shfl_xor_sync(0xffffffffu, s,  o);
        sq += __shfl_xor_sync(0xffffffffu, sq, o);
    }
    float mu = s * (1.f / DD);
    float var = sq * (1.f / DD) - mu * mu;
    float rs = rsqrtf(var + 1e-5f);

    const float* yo = g_yo + (row >> 7) * DD;   // row/T, T=128
    float s2 = 0.f, q2 = 0.f;
    #pragma unroll
    for (int j = 0; j < 8; j++) {
        int c = lane + 32 * j;
        float x1 = (v[j] - mu) * rs * ln1w[c] + ln1b[c];
        v[j] = x1 + yo[c];
        s2 += v[j]; q2 += v[j] * v[j];
    }
    #pragma unroll
    for (int o = 16; o > 0; o >>= 1) {
        s2 += __shfl_xor_sync(0xffffffffu, s2, o);
        q2 += __shfl_xor_sync(0xffffffffu, q2, o);
    }
    float mu2 = s2 * (1.f / DD);
    float var2 = q2 * (1.f / DD) - mu2 * mu2;
    float rs2 = rsqrtf(var2 + 1e-5f);

    float* orow = out + row * DD;
    #pragma unroll
    for (int j = 0; j < 8; j++) {
        int c = lane + 32 * j;
        orow[c] = (v[j] - mu2) * rs2 * ln2w[c] + ln2b[c];
    }
}

// ---------------------------------------------------------------------------
// Kernel 3: fused MLP, tf32 wmma.
// out = x3 + gelu(x3 @ w_fc + b_fc) @ w_pr + b_pr
// 64 rows per block, 8 warps (4x2 over 64x256 output). h stays in smem per
// 64-column jt slice; second GEMM accumulates in fp32 fragments.
// ---------------------------------------------------------------------------
__global__ void mlp_kernel(const float* __restrict__ x3,
                           const float* __restrict__ wfc, const float* __restrict__ bfc,
                           const float* __restrict__ wpr, const float* __restrict__ bpr,
                           float* __restrict__ out) {
    extern __shared__ float smem[];
    float* sX = smem;              // 64 x LDX (exact fp32 x3)
    float* sH = sX + 64 * LDX;     // 64 x LDH (gelu'd h tile)
    float* sO = sH + 64 * LDH;     // 64 x LDX (staged MLP output)

    int tid = threadIdx.x;
    int warp = tid >> 5;
    int wm = warp >> 1;            // 0..3 : 16-row strip
    int wn = warp & 1;             // 0..1 : 128-col half
    long row0 = (long)blockIdx.x * 64;

    #pragma unroll
    for (int i = 0; i < 64; i++) {
        int idx = tid + i * 256;
        int r = idx >> 8, c = idx & 255;
        sX[r * LDX + c] = x3[(row0 + r) * DD + c];
    }
    __syncthreads();

    wmma::fragment<wmma::accumulator, 16, 16, 8, float> acc[8];
    #pragma unroll
    for (int n = 0; n < 8; n++) wmma::fill_fragment(acc[n], 0.f);

    for (int jt = 0; jt < 16; jt++) {
        // ---- GEMM1: htile(64x64) = x3(64x256) @ wfc[:, jt*64 : jt*64+64]
        wmma::fragment<wmma::accumulator, 16, 16, 8, float> c1[2];
        wmma::fill_fragment(c1[0], 0.f);
        wmma::fill_fragment(c1[1], 0.f);
        for (int k = 0; k < 256; k += 8) {
            wmma::fragment<wmma::matrix_a, 16, 16, 8, wmma::precision::tf32, wmma::row_major> a;
            wmma::load_matrix_sync(a, sX + (wm * 16) * LDX + k, LDX);
            #pragma unroll
            for (int i = 0; i < a.num_elements; i++) a.x[i] = wmma::__float_to_tf32(a.x[i]);
            wmma::fragment<wmma::matrix_b, 16, 16, 8, wmma::precision::tf32, wmma::row_major> b0, b1;
            const float* bp = wfc + (long)k * 1024 + jt * 64 + wn * 32;
            wmma::load_matrix_sync(b0, bp, 1024);
            wmma::load_matrix_sync(b1, bp + 16, 1024);
            #pragma unroll
            for (int i = 0; i < b0.num_elements; i++) {
                b0.x[i] = wmma::__float_to_tf32(b0.x[i]);
                b1.x[i] = wmma::__float_to_tf32(b1.x[i]);
            }
            wmma::mma_sync(c1[0], a, b0, c1[0]);
            wmma::mma_sync(c1[1], a, b1, c1[1]);
        }
        wmma::store_matrix_sync(sH + (wm * 16) * LDH + wn * 32,      c1[0], LDH, wmma::mem_row_major);
        wmma::store_matrix_sync(sH + (wm * 16) * LDH + wn * 32 + 16, c1[1], LDH, wmma::mem_row_major);
        __syncthreads();

        // ---- bias + exact gelu on the h tile
        #pragma unroll
        for (int i = 0; i < 16; i++) {
            int idx = tid + i * 256;
            int r = idx >> 6, c = idx & 63;
            float vv = sH[r * LDH + c] + bfc[jt * 64 + c];
            sH[r * LDH + c] = 0.5f * vv * (1.f + erff(vv * 0.70710678118654752f));
        }
        __syncthreads();

        // ---- GEMM2: acc(64x256) += htile(64x64) @ wpr[jt*64 : jt*64+64, :]
        for (int k2 = 0; k2 < 64; k2 += 8) {
            wmma::fragment<wmma::matrix_a, 16, 16, 8, wmma::precision::tf32, wmma::row_major> a2;
            wmma::load_matrix_sync(a2, sH + (wm * 16) * LDH + k2, LDH);
            #pragma unroll
            for (int i = 0; i < a2.num_elements; i++) a2.x[i] = wmma::__float_to_tf32(a2.x[i]);
            #pragma unroll
            for (int n = 0; n < 8; n++) {
                wmma::fragment<wmma::matrix_b, 16, 16, 8, wmma::precision::tf32, wmma::row_major> b;
                wmma::load_matrix_sync(b, wpr + (long)(jt * 64 + k2) * 256 + wn * 128 + n * 16, 256);
                #pragma unroll
                for (int i = 0; i < b.num_elements; i++) b.x[i] = wmma::__float_to_tf32(b.x[i]);
                wmma::mma_sync(acc[n], a2, b, acc[n]);
            }
        }
        __syncthreads();   // protect sH before next jt's stores
    }

    // ---- epilogue: out = x3 + mlp + b_pr
    #pragma unroll
    for (int n = 0; n < 8; n++)
        wmma::store_matrix_sync(sO + (wm * 16) * LDX + wn * 128 + n * 16, acc[n], LDX, wmma::mem_row_major);
    __syncthreads();
    #pragma unroll
    for (int i = 0; i < 64; i++) {
        int idx = tid + i * 256;
        int r = idx >> 8, c = idx & 255;
        out[(row0 + r) * DD + c] = sX[r * LDX + c] + sO[r * LDX + c] + bpr[c];
    }
}

// ---------------------------------------------------------------------------
extern "C" void kernel_launch(void* const* d_in, const int* in_sizes, int n_in,
                              void* d_out, int out_size) {
    const float* x    = (const float*)d_in[0];
    const float* cx   = (const float*)d_in[1];
    const float* ln1w = (const float*)d_in[2];
    const float* ln1b = (const float*)d_in[3];
    // d_in[4] = wq, d_in[5] = bq : provably unused (softmax of equal logits)
    const float* wkv  = (const float*)d_in[6];
    const float* bkv  = (const float*)d_in[7];
    const float* wo   = (const float*)d_in[8];
    const float* bo   = (const float*)d_in[9];
    const float* ln2w = (const float*)d_in[10];
    const float* ln2b = (const float*)d_in[11];
    const float* wfc  = (const float*)d_in[12];
    const float* bfc  = (const float*)d_in[13];
    const float* wpr  = (const float*)d_in[14];
    const float* bpr  = (const float*)d_in[15];
    float* out = (float*)d_out;

    cudaFuncSetAttribute(mlp_kernel, cudaFuncAttributeMaxDynamicSharedMemorySize, MLP_SMEM_BYTES);

    yo_kernel<<<NBA / 16, 256>>>(cx, wkv, bkv, wo, bo);
    prep_kernel<<<NROWS / 8, 256>>>(x, ln1w, ln1b, ln2w, ln2b, out);
    mlp_kernel<<<NROWS / 64, 256, MLP_SMEM_BYTES>>>(out, wfc, bfc, wpr, bpr, out);
}

// round 4
// speedup vs baseline: 4.6103x; 4.6103x over previous
#include <cstdint>
#include <cuda_runtime.h>
#include <cuda_bf16.h>
#include <mma.h>
#include <math.h>

using namespace nvcuda;

#define DD   256
#define NBA  1024      // B*A
#define TT   128

// MLP kernel shared-memory layout (bytes)
#define LDXB 264       // bf16 elems per row of x3 tile (256 + 8 pad)
#define LDW1 72        // bf16: wfc tile 256 x 64 (+8 pad)
#define LDW2 264       // bf16: wpr tile 64 x 256 (+8 pad)
#define LDH  72        // h tile 128 x 64 (+8 pad)
#define OFF_WFC  67584                     // 128*LDXB*2
#define OFF_WPR  (OFF_WFC + 36864)        // + 256*LDW1*2
#define OFF_HF   (OFF_WPR + 33792)        // + 64*LDW2*2
#define OFF_HB   (OFF_HF  + 36864)        // + 128*LDH*4
#define SMEM_TOTAL (OFF_HB + 18432)       // + 128*LDH*2  = 193536 B

__device__ __nv_bfloat16 g_wfcb[256 * 1024];
__device__ __nv_bfloat16 g_wprb[1024 * 256];
__device__ float g_yo[NBA * DD];

// ---------------------------------------------------------------------------
__device__ __forceinline__ void cp16(void* sdst, const void* gsrc) {
    unsigned int s = (unsigned int)__cvta_generic_to_shared(sdst);
    asm volatile("cp.async.cg.shared.global [%0], [%1], 16;" :: "r"(s), "l"(gsrc));
}
__device__ __forceinline__ void cp_commit() { asm volatile("cp.async.commit_group;"); }
__device__ __forceinline__ void cp_wait1()  { asm volatile("cp.async.wait_group 1;"); }

// ---------------------------------------------------------------------------
// Weights fp32 -> bf16 once per launch (deterministic). 65536 float4 per mat.
// ---------------------------------------------------------------------------
__global__ void convert_kernel(const float* __restrict__ wfc, const float* __restrict__ wpr) {
    int i = blockIdx.x * blockDim.x + threadIdx.x;   // 0..65535
    float4 a = ((const float4*)wfc)[i];
    ((__nv_bfloat162*)g_wfcb)[i * 2]     = __floats2bfloat162_rn(a.x, a.y);
    ((__nv_bfloat162*)g_wfcb)[i * 2 + 1] = __floats2bfloat162_rn(a.z, a.w);
    float4 b = ((const float4*)wpr)[i];
    ((__nv_bfloat162*)g_wprb)[i * 2]     = __floats2bfloat162_rn(b.x, b.y);
    ((__nv_bfloat162*)g_wprb)[i * 2 + 1] = __floats2bfloat162_rn(b.z, b.w);
}

// ---------------------------------------------------------------------------
// yo[b,a,:] = ((cx @ wkv)[:, D:2D] + bkv[D:2D]) @ wo + bo.  4 rows/block, grid 256.
// ---------------------------------------------------------------------------
__global__ void yo_kernel(const float* __restrict__ cx, const float* __restrict__ wkv,
                          const float* __restrict__ bkv, const float* __restrict__ wo,
                          const float* __restrict__ bo) {
    __shared__ float sCX[4][DD];
    __shared__ float sV[4][DD];
    int tid = threadIdx.x;
    int r0 = blockIdx.x * 4;
    #pragma unroll
    for (int i = 0; i < 4; i++) sCX[i][tid] = cx[(r0 + i) * DD + tid];
    __syncthreads();

    float acc[4];
    #pragma unroll
    for (int i = 0; i < 4; i++) acc[i] = bkv[DD + tid];
    for (int c = 0; c < DD; c++) {
        float w = wkv[c * 512 + DD + tid];
        #pragma unroll
        for (int i = 0; i < 4; i++) acc[i] += sCX[i][c] * w;
    }
    #pragma unroll
    for (int i = 0; i < 4; i++) sV[i][tid] = acc[i];
    __syncthreads();

    float a2[4];
    #pragma unroll
    for (int i = 0; i < 4; i++) a2[i] = bo[tid];
    for (int k = 0; k < DD; k++) {
        float w = wo[k * DD + tid];
        #pragma unroll
        for (int i = 0; i < 4; i++) a2[i] += sV[i][k] * w;
    }
    #pragma unroll
    for (int i = 0; i < 4; i++) g_yo[(r0 + i) * DD + tid] = a2[i];
}

// ---------------------------------------------------------------------------
// Fused: LN1 -> +yo -> LN2 -> (bf16 wmma MLP, smem-staged, cp.async) -> +x3
// One block per (b,a) = 128 rows. 512 threads, 16 warps (4x4).
// ---------------------------------------------------------------------------
__global__ void __launch_bounds__(512, 1)
mlp_kernel(const float* __restrict__ x,
           const float* __restrict__ ln1w, const float* __restrict__ ln1b,
           const float* __restrict__ ln2w, const float* __restrict__ ln2b,
           const float* __restrict__ bfc,  const float* __restrict__ bpr,
           float* __restrict__ out) {
    extern __shared__ char smem[];
    __nv_bfloat16* sXb  = (__nv_bfloat16*)(smem);
    __nv_bfloat16* sWfc = (__nv_bfloat16*)(smem + OFF_WFC);
    __nv_bfloat16* sWpr = (__nv_bfloat16*)(smem + OFF_WPR);
    float*         sHf  = (float*)        (smem + OFF_HF);
    __nv_bfloat16* sHb  = (__nv_bfloat16*)(smem + OFF_HB);

    int tid  = threadIdx.x;
    int warp = tid >> 5;
    int lane = tid & 31;
    int wm = warp >> 2, wn = warp & 3;
    int ba = blockIdx.x;
    size_t row0 = (size_t)ba * TT;

    // -------- prefetch wfc tile jt=0 (overlaps the LN phase)
    #pragma unroll
    for (int t = 0; t < 4; t++) {
        int idx = tid + t * 512, r = idx >> 3, c8 = idx & 7;
        cp16(sWfc + r * LDW1 + c8 * 8, g_wfcb + (size_t)r * 1024 + c8 * 8);
    }
    cp_commit();

    // -------- LN phase: 8 rows per warp
    float lw1[8], lb1[8], lw2[8], lb2[8], yo[8];
    {
        float4 a, b;
        a = ((const float4*)ln1w)[lane * 2]; b = ((const float4*)ln1w)[lane * 2 + 1];
        lw1[0]=a.x; lw1[1]=a.y; lw1[2]=a.z; lw1[3]=a.w; lw1[4]=b.x; lw1[5]=b.y; lw1[6]=b.z; lw1[7]=b.w;
        a = ((const float4*)ln1b)[lane * 2]; b = ((const float4*)ln1b)[lane * 2 + 1];
        lb1[0]=a.x; lb1[1]=a.y; lb1[2]=a.z; lb1[3]=a.w; lb1[4]=b.x; lb1[5]=b.y; lb1[6]=b.z; lb1[7]=b.w;
        a = ((const float4*)ln2w)[lane * 2]; b = ((const float4*)ln2w)[lane * 2 + 1];
        lw2[0]=a.x; lw2[1]=a.y; lw2[2]=a.z; lw2[3]=a.w; lw2[4]=b.x; lw2[5]=b.y; lw2[6]=b.z; lw2[7]=b.w;
        a = ((const float4*)ln2b)[lane * 2]; b = ((const float4*)ln2b)[lane * 2 + 1];
        lb2[0]=a.x; lb2[1]=a.y; lb2[2]=a.z; lb2[3]=a.w; lb2[4]=b.x; lb2[5]=b.y; lb2[6]=b.z; lb2[7]=b.w;
        const float* yor = g_yo + (size_t)ba * DD;
        a = ((const float4*)yor)[lane * 2]; b = ((const float4*)yor)[lane * 2 + 1];
        yo[0]=a.x; yo[1]=a.y; yo[2]=a.z; yo[3]=a.w; yo[4]=b.x; yo[5]=b.y; yo[6]=b.z; yo[7]=b.w;
    }
    for (int rr = 0; rr < 8; rr++) {
        int row = warp * 8 + rr;
        const float4* xr = (const float4*)(x + (row0 + row) * DD);
        float v[8];
        { float4 u0 = xr[lane * 2], u1 = xr[lane * 2 + 1];
          v[0]=u0.x; v[1]=u0.y; v[2]=u0.z; v[3]=u0.w; v[4]=u1.x; v[5]=u1.y; v[6]=u1.z; v[7]=u1.w; }
        float s = 0.f, q = 0.f;
        #pragma unroll
        for (int j = 0; j < 8; j++) { s += v[j]; q += v[j] * v[j]; }
        #pragma unroll
        for (int o = 16; o > 0; o >>= 1) { s += __shfl_xor_sync(~0u, s, o); q += __shfl_xor_sync(~0u, q, o); }
        float mu = s * (1.f / DD);
        float rs = rsqrtf(q * (1.f / DD) - mu * mu + 1e-5f);

        float tv[8]; s = 0.f; q = 0.f;
        #pragma unroll
        for (int j = 0; j < 8; j++) {
            tv[j] = (v[j] - mu) * rs * lw1[j] + lb1[j] + yo[j];
            s += tv[j]; q += tv[j] * tv[j];
        }
        #pragma unroll
        for (int o = 16; o > 0; o >>= 1) { s += __shfl_xor_sync(~0u, s, o); q += __shfl_xor_sync(~0u, q, o); }
        float mu2 = s * (1.f / DD);
        float rs2 = rsqrtf(q * (1.f / DD) - mu2 * mu2 + 1e-5f);
        #pragma unroll
        for (int j = 0; j < 8; j++) v[j] = (tv[j] - mu2) * rs2 * lw2[j] + lb2[j];

        float* orow = out + (row0 + row) * DD;
        float4 o0 = make_float4(v[0], v[1], v[2], v[3]);
        float4 o1 = make_float4(v[4], v[5], v[6], v[7]);
        ((float4*)orow)[lane * 2] = o0;
        ((float4*)orow)[lane * 2 + 1] = o1;

        __nv_bfloat162 p0 = __floats2bfloat162_rn(v[0], v[1]);
        __nv_bfloat162 p1 = __floats2bfloat162_rn(v[2], v[3]);
        __nv_bfloat162 p2 = __floats2bfloat162_rn(v[4], v[5]);
        __nv_bfloat162 p3 = __floats2bfloat162_rn(v[6], v[7]);
        uint4 pk;
        pk.x = *(unsigned*)&p0; pk.y = *(unsigned*)&p1; pk.z = *(unsigned*)&p2; pk.w = *(unsigned*)&p3;
        *(uint4*)(sXb + row * LDXB + lane * 8) = pk;
    }
    __syncthreads();

    // -------- MLP mainloop
    wmma::fragment<wmma::accumulator, 16, 16, 16, float> acc[2][4];
    #pragma unroll
    for (int m = 0; m < 2; m++)
        #pragma unroll
        for (int n = 0; n < 4; n++) wmma::fill_fragment(acc[m][n], 0.f);

    for (int jt = 0; jt < 16; jt++) {
        // prefetch wpr_jt
        #pragma unroll
        for (int t = 0; t < 4; t++) {
            int idx = tid + t * 512, r = idx >> 5, c8 = idx & 31;
            cp16(sWpr + r * LDW2 + c8 * 8, g_wprb + (size_t)(jt * 64 + r) * 256 + c8 * 8);
        }
        cp_commit();
        cp_wait1();              // wfc_jt resident
        __syncthreads();

        // GEMM1: h(128x64) = x3b(128x256) @ wfcT(256x64)
        wmma::fragment<wmma::accumulator, 16, 16, 16, float> c0, c1;
        wmma::fill_fragment(c0, 0.f); wmma::fill_fragment(c1, 0.f);
        #pragma unroll
        for (int k = 0; k < 256; k += 16) {
            wmma::fragment<wmma::matrix_a, 16, 16, 16, __nv_bfloat16, wmma::row_major> a0, a1;
            wmma::fragment<wmma::matrix_b, 16, 16, 16, __nv_bfloat16, wmma::row_major> b;
            wmma::load_matrix_sync(a0, sXb + (wm * 32) * LDXB + k, LDXB);
            wmma::load_matrix_sync(a1, sXb + (wm * 32 + 16) * LDXB + k, LDXB);
            wmma::load_matrix_sync(b, sWfc + k * LDW1 + wn * 16, LDW1);
            wmma::mma_sync(c0, a0, b, c0);
            wmma::mma_sync(c1, a1, b, c1);
        }
        wmma::store_matrix_sync(sHf + (wm * 32) * LDH + wn * 16, c0, LDH, wmma::mem_row_major);
        wmma::store_matrix_sync(sHf + (wm * 32 + 16) * LDH + wn * 16, c1, LDH, wmma::mem_row_major);
        __syncthreads();

        // bias + exact gelu -> bf16
        #pragma unroll
        for (int t = 0; t < 16; t++) {
            int e = tid + t * 512, r = e >> 6, c = e & 63;
            float vv = sHf[r * LDH + c] + bfc[jt * 64 + c];
            float g = 0.5f * vv * (1.f + erff(vv * 0.70710678118654752f));
            sHb[r * LDH + c] = __float2bfloat16_rn(g);
        }
        // prefetch wfc_{jt+1}
        if (jt < 15) {
            #pragma unroll
            for (int t = 0; t < 4; t++) {
                int idx = tid + t * 512, r = idx >> 3, c8 = idx & 7;
                cp16(sWfc + r * LDW1 + c8 * 8, g_wfcb + (size_t)r * 1024 + (jt + 1) * 64 + c8 * 8);
            }
        }
        cp_commit();             // (empty group at jt=15 keeps the wait math right)
        cp_wait1();              // wpr_jt resident
        __syncthreads();

        // GEMM2: acc(128x256) += gelu_h(128x64) @ wprT(64x256)
        #pragma unroll
        for (int k2 = 0; k2 < 64; k2 += 16) {
            wmma::fragment<wmma::matrix_a, 16, 16, 16, __nv_bfloat16, wmma::row_major> a0, a1;
            wmma::load_matrix_sync(a0, sHb + (wm * 32) * LDH + k2, LDH);
            wmma::load_matrix_sync(a1, sHb + (wm * 32 + 16) * LDH + k2, LDH);
            #pragma unroll
            for (int n = 0; n < 4; n++) {
                wmma::fragment<wmma::matrix_b, 16, 16, 16, __nv_bfloat16, wmma::row_major> b;
                wmma::load_matrix_sync(b, sWpr + k2 * LDW2 + wn * 64 + n * 16, LDW2);
                wmma::mma_sync(acc[0][n], a0, b, acc[0][n]);
                wmma::mma_sync(acc[1][n], a1, b, acc[1][n]);
            }
        }
        __syncthreads();
    }

    // -------- epilogue: out = x3 + mlp + b_pr  (4 column passes via sHf)
    for (int n = 0; n < 4; n++) {
        __syncthreads();
        wmma::store_matrix_sync(sHf + (wm * 32) * LDH + wn * 16, acc[0][n], LDH, wmma::mem_row_major);
        wmma::store_matrix_sync(sHf + (wm * 32 + 16) * LDH + wn * 16, acc[1][n], LDH, wmma::mem_row_major);
        __syncthreads();
        #pragma unroll
        for (int t = 0; t < 16; t++) {
            int e = tid + t * 512, r = e >> 6, lc = e & 63;
            int strip = lc >> 4, w = lc & 15;
            int gcol = strip * 64 + n * 16 + w;
            size_t gi = (row0 + r) * DD + gcol;
            out[gi] = out[gi] + sHf[r * LDH + lc] + bpr[gcol];
        }
    }
}

// ---------------------------------------------------------------------------
extern "C" void kernel_launch(void* const* d_in, const int* in_sizes, int n_in,
                              void* d_out, int out_size) {
    const float* x    = (const float*)d_in[0];
    const float* cx   = (const float*)d_in[1];
    const float* ln1w = (const float*)d_in[2];
    const float* ln1b = (const float*)d_in[3];
    // d_in[4]=wq, d_in[5]=bq: unused (softmax of equal logits is uniform; V constant over keys)
    const float* wkv  = (const float*)d_in[6];
    const float* bkv  = (const float*)d_in[7];
    const float* wo   = (const float*)d_in[8];
    const float* bo   = (const float*)d_in[9];
    const float* ln2w = (const float*)d_in[10];
    const float* ln2b = (const float*)d_in[11];
    const float* wfc  = (const float*)d_in[12];
    const float* bfc  = (const float*)d_in[13];
    const float* wpr  = (const float*)d_in[14];
    const float* bpr  = (const float*)d_in[15];
    float* out = (float*)d_out;

    cudaFuncSetAttribute(mlp_kernel, cudaFuncAttributeMaxDynamicSharedMemorySize, SMEM_TOTAL);

    convert_kernel<<<256, 256>>>(wfc, wpr);
    yo_kernel<<<256, 256>>>(cx, wkv, bkv, wo, bo);
    mlp_kernel<<<NBA, 512, SMEM_TOTAL>>>(x, ln1w, ln1b, ln2w, ln2b, bfc, bpr, out);
}

// round 5
// speedup vs baseline: 4.6213x; 1.0024x over previous
#include <cstdint>
#include <cuda_runtime.h>
#include <cuda_bf16.h>
#include <mma.h>
#include <math.h>

using namespace nvcuda;

#define DD   256
#define NBA  1024      // B*A
#define TT   128

// MLP kernel shared-memory layout (bytes)
#define LDXB 264       // bf16 elems per row of x3 tile (256 + 8 pad)
#define LDW1 72        // bf16: wfc tile 256 x 64 (+8 pad)
#define LDW2 264       // bf16: wpr tile 64 x 256 (+8 pad)
#define LDH  72        // h tile 128 x 64 (+8 pad)
#define OFF_WFC  67584                     // 128*LDXB*2
#define OFF_WPR  (OFF_WFC + 36864)        // + 256*LDW1*2
#define OFF_HF   (OFF_WPR + 33792)        // + 64*LDW2*2
#define OFF_HB   (OFF_HF  + 36864)        // + 128*LDH*4
#define SMEM_TOTAL (OFF_HB + 18432)       // + 128*LDH*2  = 193536 B

__device__ __nv_bfloat16 g_wfcb[256 * 1024];
__device__ __nv_bfloat16 g_wprb[1024 * 256];
__device__ float g_yo[NBA * DD];

// ---------------------------------------------------------------------------
__device__ __forceinline__ void cp16(void* sdst, const void* gsrc) {
    unsigned int s = (unsigned int)__cvta_generic_to_shared(sdst);
    asm volatile("cp.async.cg.shared.global [%0], [%1], 16;" :: "r"(s), "l"(gsrc));
}
__device__ __forceinline__ void cp_commit() { asm volatile("cp.async.commit_group;"); }
__device__ __forceinline__ void cp_wait1()  { asm volatile("cp.async.wait_group 1;"); }

// ---------------------------------------------------------------------------
// Weights fp32 -> bf16 once per launch (deterministic). 65536 float4 per mat.
// ---------------------------------------------------------------------------
__global__ void convert_kernel(const float* __restrict__ wfc, const float* __restrict__ wpr) {
    int i = blockIdx.x * blockDim.x + threadIdx.x;   // 0..65535
    float4 a = ((const float4*)wfc)[i];
    ((__nv_bfloat162*)g_wfcb)[i * 2]     = __floats2bfloat162_rn(a.x, a.y);
    ((__nv_bfloat162*)g_wfcb)[i * 2 + 1] = __floats2bfloat162_rn(a.z, a.w);
    float4 b = ((const float4*)wpr)[i];
    ((__nv_bfloat162*)g_wprb)[i * 2]     = __floats2bfloat162_rn(b.x, b.y);
    ((__nv_bfloat162*)g_wprb)[i * 2 + 1] = __floats2bfloat162_rn(b.z, b.w);
}

// ---------------------------------------------------------------------------
// yo[b,a,:] = ((cx @ wkv)[:, D:2D] + bkv[D:2D]) @ wo + bo.  4 rows/block, grid 256.
// ---------------------------------------------------------------------------
__global__ void yo_kernel(const float* __restrict__ cx, const float* __restrict__ wkv,
                          const float* __restrict__ bkv, const float* __restrict__ wo,
                          const float* __restrict__ bo) {
    __shared__ float sCX[4][DD];
    __shared__ float sV[4][DD];
    int tid = threadIdx.x;
    int r0 = blockIdx.x * 4;
    #pragma unroll
    for (int i = 0; i < 4; i++) sCX[i][tid] = cx[(r0 + i) * DD + tid];
    __syncthreads();

    float acc[4];
    #pragma unroll
    for (int i = 0; i < 4; i++) acc[i] = bkv[DD + tid];
    for (int c = 0; c < DD; c++) {
        float w = wkv[c * 512 + DD + tid];
        #pragma unroll
        for (int i = 0; i < 4; i++) acc[i] += sCX[i][c] * w;
    }
    #pragma unroll
    for (int i = 0; i < 4; i++) sV[i][tid] = acc[i];
    __syncthreads();

    float a2[4];
    #pragma unroll
    for (int i = 0; i < 4; i++) a2[i] = bo[tid];
    for (int k = 0; k < DD; k++) {
        float w = wo[k * DD + tid];
        #pragma unroll
        for (int i = 0; i < 4; i++) a2[i] += sV[i][k] * w;
    }
    #pragma unroll
    for (int i = 0; i < 4; i++) g_yo[(r0 + i) * DD + tid] = a2[i];
}

// ---------------------------------------------------------------------------
// Fused: LN1 -> +yo -> LN2 -> (bf16 wmma MLP, smem-staged, cp.async) -> +x3
// One block per (b,a) = 128 rows. 512 threads, 16 warps (4x4).
// ---------------------------------------------------------------------------
__global__ void __launch_bounds__(512, 1)
mlp_kernel(const float* __restrict__ x,
           const float* __restrict__ ln1w, const float* __restrict__ ln1b,
           const float* __restrict__ ln2w, const float* __restrict__ ln2b,
           const float* __restrict__ bfc,  const float* __restrict__ bpr,
           float* __restrict__ out) {
    extern __shared__ char smem[];
    __nv_bfloat16* sXb  = (__nv_bfloat16*)(smem);
    __nv_bfloat16* sWfc = (__nv_bfloat16*)(smem + OFF_WFC);
    __nv_bfloat16* sWpr = (__nv_bfloat16*)(smem + OFF_WPR);
    float*         sHf  = (float*)        (smem + OFF_HF);
    __nv_bfloat16* sHb  = (__nv_bfloat16*)(smem + OFF_HB);

    int tid  = threadIdx.x;
    int warp = tid >> 5;
    int lane = tid & 31;
    int wm = warp >> 2, wn = warp & 3;
    int ba = blockIdx.x;
    size_t row0 = (size_t)ba * TT;

    // -------- prefetch wfc tile jt=0 (overlaps the LN phase)
    #pragma unroll
    for (int t = 0; t < 4; t++) {
        int idx = tid + t * 512, r = idx >> 3, c8 = idx & 7;
        cp16(sWfc + r * LDW1 + c8 * 8, g_wfcb + (size_t)r * 1024 + c8 * 8);
    }
    cp_commit();

    // -------- LN phase: 8 rows per warp
    float lw1[8], lb1[8], lw2[8], lb2[8], yo[8];
    {
        float4 a, b;
        a = ((const float4*)ln1w)[lane * 2]; b = ((const float4*)ln1w)[lane * 2 + 1];
        lw1[0]=a.x; lw1[1]=a.y; lw1[2]=a.z; lw1[3]=a.w; lw1[4]=b.x; lw1[5]=b.y; lw1[6]=b.z; lw1[7]=b.w;
        a = ((const float4*)ln1b)[lane * 2]; b = ((const float4*)ln1b)[lane * 2 + 1];
        lb1[0]=a.x; lb1[1]=a.y; lb1[2]=a.z; lb1[3]=a.w; lb1[4]=b.x; lb1[5]=b.y; lb1[6]=b.z; lb1[7]=b.w;
        a = ((const float4*)ln2w)[lane * 2]; b = ((const float4*)ln2w)[lane * 2 + 1];
        lw2[0]=a.x; lw2[1]=a.y; lw2[2]=a.z; lw2[3]=a.w; lw2[4]=b.x; lw2[5]=b.y; lw2[6]=b.z; lw2[7]=b.w;
        a = ((const float4*)ln2b)[lane * 2]; b = ((const float4*)ln2b)[lane * 2 + 1];
        lb2[0]=a.x; lb2[1]=a.y; lb2[2]=a.z; lb2[3]=a.w; lb2[4]=b.x; lb2[5]=b.y; lb2[6]=b.z; lb2[7]=b.w;
        const float* yor = g_yo + (size_t)ba * DD;
        a = ((const float4*)yor)[lane * 2]; b = ((const float4*)yor)[lane * 2 + 1];
        yo[0]=a.x; yo[1]=a.y; yo[2]=a.z; yo[3]=a.w; yo[4]=b.x; yo[5]=b.y; yo[6]=b.z; yo[7]=b.w;
    }
    for (int rr = 0; rr < 8; rr++) {
        int row = warp * 8 + rr;
        const float4* xr = (const float4*)(x + (row0 + row) * DD);
        float v[8];
        { float4 u0 = xr[lane * 2], u1 = xr[lane * 2 + 1];
          v[0]=u0.x; v[1]=u0.y; v[2]=u0.z; v[3]=u0.w; v[4]=u1.x; v[5]=u1.y; v[6]=u1.z; v[7]=u1.w; }
        float s = 0.f, q = 0.f;
        #pragma unroll
        for (int j = 0; j < 8; j++) { s += v[j]; q += v[j] * v[j]; }
        #pragma unroll
        for (int o = 16; o > 0; o >>= 1) { s += __shfl_xor_sync(~0u, s, o); q += __shfl_xor_sync(~0u, q, o); }
        float mu = s * (1.f / DD);
        float rs = rsqrtf(q * (1.f / DD) - mu * mu + 1e-5f);

        float tv[8]; s = 0.f; q = 0.f;
        #pragma unroll
        for (int j = 0; j < 8; j++) {
            tv[j] = (v[j] - mu) * rs * lw1[j] + lb1[j] + yo[j];
            s += tv[j]; q += tv[j] * tv[j];
        }
        #pragma unroll
        for (int o = 16; o > 0; o >>= 1) { s += __shfl_xor_sync(~0u, s, o); q += __shfl_xor_sync(~0u, q, o); }
        float mu2 = s * (1.f / DD);
        float rs2 = rsqrtf(q * (1.f / DD) - mu2 * mu2 + 1e-5f);
        #pragma unroll
        for (int j = 0; j < 8; j++) v[j] = (tv[j] - mu2) * rs2 * lw2[j] + lb2[j];

        float* orow = out + (row0 + row) * DD;
        float4 o0 = make_float4(v[0], v[1], v[2], v[3]);
        float4 o1 = make_float4(v[4], v[5], v[6], v[7]);
        ((float4*)orow)[lane * 2] = o0;
        ((float4*)orow)[lane * 2 + 1] = o1;

        __nv_bfloat162 p0 = __floats2bfloat162_rn(v[0], v[1]);
        __nv_bfloat162 p1 = __floats2bfloat162_rn(v[2], v[3]);
        __nv_bfloat162 p2 = __floats2bfloat162_rn(v[4], v[5]);
        __nv_bfloat162 p3 = __floats2bfloat162_rn(v[6], v[7]);
        uint4 pk;
        pk.x = *(unsigned*)&p0; pk.y = *(unsigned*)&p1; pk.z = *(unsigned*)&p2; pk.w = *(unsigned*)&p3;
        *(uint4*)(sXb + row * LDXB + lane * 8) = pk;
    }
    __syncthreads();

    // -------- MLP mainloop
    wmma::fragment<wmma::accumulator, 16, 16, 16, float> acc[2][4];
    #pragma unroll
    for (int m = 0; m < 2; m++)
        #pragma unroll
        for (int n = 0; n < 4; n++) wmma::fill_fragment(acc[m][n], 0.f);

    for (int jt = 0; jt < 16; jt++) {
        // prefetch wpr_jt
        #pragma unroll
        for (int t = 0; t < 4; t++) {
            int idx = tid + t * 512, r = idx >> 5, c8 = idx & 31;
            cp16(sWpr + r * LDW2 + c8 * 8, g_wprb + (size_t)(jt * 64 + r) * 256 + c8 * 8);
        }
        cp_commit();
        cp_wait1();              // wfc_jt resident
        __syncthreads();

        // GEMM1: h(128x64) = x3b(128x256) @ wfcT(256x64)
        wmma::fragment<wmma::accumulator, 16, 16, 16, float> c0, c1;
        wmma::fill_fragment(c0, 0.f); wmma::fill_fragment(c1, 0.f);
        #pragma unroll
        for (int k = 0; k < 256; k += 16) {
            wmma::fragment<wmma::matrix_a, 16, 16, 16, __nv_bfloat16, wmma::row_major> a0, a1;
            wmma::fragment<wmma::matrix_b, 16, 16, 16, __nv_bfloat16, wmma::row_major> b;
            wmma::load_matrix_sync(a0, sXb + (wm * 32) * LDXB + k, LDXB);
            wmma::load_matrix_sync(a1, sXb + (wm * 32 + 16) * LDXB + k, LDXB);
            wmma::load_matrix_sync(b, sWfc + k * LDW1 + wn * 16, LDW1);
            wmma::mma_sync(c0, a0, b, c0);
            wmma::mma_sync(c1, a1, b, c1);
        }
        wmma::store_matrix_sync(sHf + (wm * 32) * LDH + wn * 16, c0, LDH, wmma::mem_row_major);
        wmma::store_matrix_sync(sHf + (wm * 32 + 16) * LDH + wn * 16, c1, LDH, wmma::mem_row_major);
        __syncthreads();

        // bias + exact gelu -> bf16
        #pragma unroll
        for (int t = 0; t < 16; t++) {
            int e = tid + t * 512, r = e >> 6, c = e & 63;
            float vv = sHf[r * LDH + c] + bfc[jt * 64 + c];
            float g = 0.5f * vv * (1.f + erff(vv * 0.70710678118654752f));
            sHb[r * LDH + c] = __float2bfloat16_rn(g);
        }
        // prefetch wfc_{jt+1}
        if (jt < 15) {
            #pragma unroll
            for (int t = 0; t < 4; t++) {
                int idx = tid + t * 512, r = idx >> 3, c8 = idx & 7;
                cp16(sWfc + r * LDW1 + c8 * 8, g_wfcb + (size_t)r * 1024 + (jt + 1) * 64 + c8 * 8);
            }
        }
        cp_commit();             // (empty group at jt=15 keeps the wait math right)
        cp_wait1();              // wpr_jt resident
        __syncthreads();

        // GEMM2: acc(128x256) += gelu_h(128x64) @ wprT(64x256)
        #pragma unroll
        for (int k2 = 0; k2 < 64; k2 += 16) {
            wmma::fragment<wmma::matrix_a, 16, 16, 16, __nv_bfloat16, wmma::row_major> a0, a1;
            wmma::load_matrix_sync(a0, sHb + (wm * 32) * LDH + k2, LDH);
            wmma::load_matrix_sync(a1, sHb + (wm * 32 + 16) * LDH + k2, LDH);
            #pragma unroll
            for (int n = 0; n < 4; n++) {
                wmma::fragment<wmma::matrix_b, 16, 16, 16, __nv_bfloat16, wmma::row_major> b;
                wmma::load_matrix_sync(b, sWpr + k2 * LDW2 + wn * 64 + n * 16, LDW2);
                wmma::mma_sync(acc[0][n], a0, b, acc[0][n]);
                wmma::mma_sync(acc[1][n], a1, b, acc[1][n]);
            }
        }
        __syncthreads();
    }

    // -------- epilogue: out = x3 + mlp + b_pr  (4 column passes via sHf)
    for (int n = 0; n < 4; n++) {
        __syncthreads();
        wmma::store_matrix_sync(sHf + (wm * 32) * LDH + wn * 16, acc[0][n], LDH, wmma::mem_row_major);
        wmma::store_matrix_sync(sHf + (wm * 32 + 16) * LDH + wn * 16, acc[1][n], LDH, wmma::mem_row_major);
        __syncthreads();
        #pragma unroll
        for (int t = 0; t < 16; t++) {
            int e = tid + t * 512, r = e >> 6, lc = e & 63;
            int strip = lc >> 4, w = lc & 15;
            int gcol = strip * 64 + n * 16 + w;
            size_t gi = (row0 + r) * DD + gcol;
            out[gi] = out[gi] + sHf[r * LDH + lc] + bpr[gcol];
        }
    }
}

// ---------------------------------------------------------------------------
extern "C" void kernel_launch(void* const* d_in, const int* in_sizes, int n_in,
                              void* d_out, int out_size) {
    const float* x    = (const float*)d_in[0];
    const float* cx   = (const float*)d_in[1];
    const float* ln1w = (const float*)d_in[2];
    const float* ln1b = (const float*)d_in[3];
    // d_in[4]=wq, d_in[5]=bq: unused (softmax of equal logits is uniform; V constant over keys)
    const float* wkv  = (const float*)d_in[6];
    const float* bkv  = (const float*)d_in[7];
    const float* wo   = (const float*)d_in[8];
    const float* bo   = (const float*)d_in[9];
    const float* ln2w = (const float*)d_in[10];
    const float* ln2b = (const float*)d_in[11];
    const float* wfc  = (const float*)d_in[12];
    const float* bfc  = (const float*)d_in[13];
    const float* wpr  = (const float*)d_in[14];
    const float* bpr  = (const float*)d_in[15];
    float* out = (float*)d_out;

    cudaFuncSetAttribute(mlp_kernel, cudaFuncAttributeMaxDynamicSharedMemorySize, SMEM_TOTAL);

    convert_kernel<<<256, 256>>>(wfc, wpr);
    yo_kernel<<<256, 256>>>(cx, wkv, bkv, wo, bo);
    mlp_kernel<<<NBA, 512, SMEM_TOTAL>>>(x, ln1w, ln1b, ln2w, ln2b, bfc, bpr, out);
}